// round 16
// baseline (speedup 1.0000x reference)
#include <cuda_runtime.h>
#include <cstdint>

#define CIN 72
#define COUT 72
#define NSPAT 32768          // 32*32*32
#define NB 8
#define NTOT (NB*NSPAT)
#define OD 30
#define OSPAT (OD*OD*OD)     // 27000

typedef unsigned long long u64;
typedef unsigned int u32;

// -------- device scratch (no allocations allowed) --------
__device__ float g_psum[NB][CIN];
__device__ float g_psq[NB][CIN];
__device__ float g_sc[CIN];
__device__ float g_bias[COUT];
__device__ float g_C[4374];            // basis coeffs per j: [(e*27+tap)*18 + (b2*9+s)]
__device__ u64   g_w2d[3*24*2*8];      // duplicated {w,w}: [i][(g*2+b2)*8+u]
// z layout: channel c = s*48 + g*2 + b2   (s-major: mix block reads 48 contiguous rows)
__device__ __align__(16) float g_z[(size_t)NB*432u*27000u];   // intermediate (373 MB)

// -------- packed f32x2 helpers --------
__device__ __forceinline__ u64 pack2(float a){
    u64 r; asm("mov.b64 %0, {%1, %1};" : "=l"(r) : "f"(a)); return r;
}
__device__ __forceinline__ void fma2(u64& d, u64 a, u64 b){
    asm("fma.rn.f32x2 %0, %1, %2, %0;" : "+l"(d) : "l"(a), "l"(b));
}
__device__ __forceinline__ void unpack2(u64 v, float& lo, float& hi){
    asm("mov.b64 {%0, %1}, %2;" : "=f"(lo), "=f"(hi) : "l"(v));
}
__device__ __forceinline__ u32 smem_u32(const void* p){
    u32 a; asm("{ .reg .u64 t; cvta.to.shared.u64 t, %1; cvt.u32.u64 %0, t; }" : "=r"(a) : "l"(p));
    return a;
}
__device__ __forceinline__ void cp16(u32 dst, const void* src){
    asm volatile("cp.async.ca.shared.global [%0], [%1], 16;" :: "r"(dst), "l"(src));
}
__device__ __forceinline__ void cp_commit(){ asm volatile("cp.async.commit_group;" ::: "memory"); }
__device__ __forceinline__ void cp_wait_all(){ asm volatile("cp.async.wait_group 0;" ::: "memory"); }

__device__ __forceinline__ void s_to_id(int s, int& i, int& d){
    if (s == 0){ i = 0; d = 0; }
    else if (s < 4){ i = 1; d = s - 1; }
    else { i = 2; d = s - 4; }
}

// -------- 1) init: zero stats accumulators + build basis coeff table --------
__global__ void init_kernel(
    const float* b00, const float* b01, const float* b02,
    const float* b10, const float* b11, const float* b12,
    const float* b20, const float* b21, const float* b22){
    int idx = blockIdx.x * blockDim.x + threadIdx.x;
    if (idx < 1152){
        if (idx < 576) ((float*)g_psum)[idx] = 0.f;
        else           ((float*)g_psq)[idx - 576] = 0.f;
        return;
    }
    idx -= 1152;
    if (idx >= 4374) return;
    int j, off;
    if (idx < 486){ j = 0; off = 0; }
    else if (idx < 1944){ j = 1; off = 486; }
    else { j = 2; off = 1944; }
    int rem = idx - off;
    int tt  = rem % 18;
    int et  = rem / 18;
    int tap = et % 27;
    int e   = et / 27;
    int b2  = tt / 9, s = tt % 9;
    int i, d; s_to_id(s, i, d);
    int di = (i == 0) ? 1 : (i == 1 ? 3 : 5);
    int dj = (j == 0) ? 1 : (j == 1 ? 3 : 5);
    const float* bas;
    int sel = i*3 + j;
    switch (sel){
        case 0: bas = b00; break; case 1: bas = b01; break; case 2: bas = b02; break;
        case 3: bas = b10; break; case 4: bas = b11; break; case 5: bas = b12; break;
        case 6: bas = b20; break; case 7: bas = b21; break; default: bas = b22; break;
    }
    g_C[idx] = bas[((b2*di + d)*dj + e)*27 + tap];
}

// -------- 2) A: basis conv + fused stats; ALL batches; dj-interleaved --------
__global__ __launch_bounds__(128) void basis_conv(const float* __restrict__ x){
    __shared__ __align__(16) float sC[2430];
    __shared__ __align__(16) float sX[9720];          // [e][z3][y18][36]
    __shared__ float redS[128];
    __shared__ float redQ[128];

    const int tid = threadIdx.x;
    const int xg  = tid & 7;
    const int yr  = tid >> 3;            // 0..15
    const int x0  = xg << 2;
    const int yt  = blockIdx.x;          // 0..1
    const int oz  = blockIdx.y;          // 0..29
    const int zi  = blockIdx.z;          // 0..191
    const int b   = zi / 24;
    const int gi  = zi % 24;
    const int g   = (gi % 3) * 8 + (gi / 3);   // interleave dj = 1,3,5,...
    const int y0  = yt * 16;

    const int j  = g >> 3, v = g & 7;
    const int dj = (j == 0) ? 1 : (j == 1 ? 3 : 5);
    const int fo = (j == 0) ? 0 : (j == 1 ? 8 : 32);
    const int coff = (j == 0) ? 0 : (j == 1 ? 486 : 1944);

    const float* xc = x + ((size_t)b*CIN + fo + v*dj)*NSPAT;

    const int csz = dj * 486;
    for (int k = tid; k < csz; k += 128) sC[k] = g_C[coff + k];

    const u32 sxa = smem_u32(sX);
    const int nrows = dj * 54;
    for (int r8 = tid; r8 < nrows*8; r8 += 128){
        int r = r8 >> 3, seg = r8 & 7;
        int e = r / 54, rem = r % 54, zz = rem / 18, yy = rem % 18;
        int ys = y0 + yy; if (ys > 31) ys = 31;
        cp16(sxa + (u32)(r*36 + seg*4)*4, xc + (size_t)e*NSPAT + (oz+zz)*1024 + ys*32 + seg*4);
    }
    for (int k = tid; k < nrows*4; k += 128){
        int r = k >> 2, c = 32 + (k & 3);
        sX[r*36 + c] = 0.f;
    }
    cp_commit(); cp_wait_all();
    __syncthreads();

    // ---- fused stats: ownership = rows yy 0..15 (unclamped); planes: oz+1 always,
    //      plus plane 0 when oz==0 (zz=0) and plane 31 when oz==29 (zz=2).
    //      Pad cols (32..35) are zero -> harmless to include.
    for (int e = 0; e < dj; e++){
        float s = 0.f, q = 0.f;
        #pragma unroll
        for (int zz = 0; zz < 3; zz++){
            bool own = (zz == 1) || (zz == 0 && oz == 0) || (zz == 2 && oz == 29);
            if (!own) continue;
            const float* base = &sX[(e*3 + zz)*18*36];
            for (int k = tid; k < 16*36; k += 128){
                float vv = base[k]; s += vv; q += vv*vv;
            }
        }
        redS[tid] = s; redQ[tid] = q;
        __syncthreads();
        for (int ofs = 64; ofs > 0; ofs >>= 1){
            if (tid < ofs){ redS[tid] += redS[tid+ofs]; redQ[tid] += redQ[tid+ofs]; }
            __syncthreads();
        }
        if (tid == 0){
            atomicAdd(&g_psum[b][fo + v*dj + e], redS[0]);
            atomicAdd(&g_psq[b][fo + v*dj + e], redQ[0]);
        }
        __syncthreads();
    }

    u64 acc[9][4];
    #pragma unroll
    for (int tp = 0; tp < 9; tp++)
        #pragma unroll
        for (int vx = 0; vx < 4; vx++) acc[tp][vx] = 0ULL;

    for (int e = 0; e < dj; e++){
        #pragma unroll
        for (int kz = 0; kz < 3; kz++){
            #pragma unroll
            for (int ky = 0; ky < 3; ky++){
                const float* row = &sX[(((e*3 + kz)*18) + yr + ky)*36 + x0];
                float4 f4 = *reinterpret_cast<const float4*>(row);
                float2 f2 = *reinterpret_cast<const float2*>(row + 4);
                u64 X[6];
                X[0] = pack2(f4.x); X[1] = pack2(f4.y); X[2] = pack2(f4.z);
                X[3] = pack2(f4.w); X[4] = pack2(f2.x); X[5] = pack2(f2.y);
                const int tapb = kz*9 + ky*3;
                #pragma unroll
                for (int kx = 0; kx < 3; kx++){
                    const float* cb = &sC[(e*27 + tapb + kx)*18];
                    #pragma unroll
                    for (int tp = 0; tp < 9; tp++){
                        u64 c2 = *reinterpret_cast<const u64*>(cb + 2*tp);
                        fma2(acc[tp][0], c2, X[kx]);
                        fma2(acc[tp][1], c2, X[kx+1]);
                        fma2(acc[tp][2], c2, X[kx+2]);
                        fma2(acc[tp][3], c2, X[kx+3]);
                    }
                }
            }
        }
    }

    const int oy = y0 + yr;
    if (oy < OD){
        const size_t vbase = (size_t)(oz*OD + oy)*OD;
        float* zb = g_z + (size_t)b*432u*OSPAT;
        #pragma unroll
        for (int tp = 0; tp < 9; tp++){
            const int t0 = 2*tp, t1 = 2*tp + 1;
            const int c0 = (t0 % 9)*48 + g*2 + (t0 / 9);
            const int c1 = (t1 % 9)*48 + g*2 + (t1 / 9);
            float* z0 = zb + (size_t)c0*OSPAT + vbase;
            float* z1 = zb + (size_t)c1*OSPAT + vbase;
            #pragma unroll
            for (int vx = 0; vx < 4; vx++){
                int ox = x0 + vx;
                float lo, hi; unpack2(acc[tp][vx], lo, hi);
                if (ox < OD){ z0[ox] = lo; z1[ox] = hi; }
            }
        }
    }
}

// -------- 3) prep_w: scales / bias / duplicated mix weights (needs stats) --------
__global__ void prep_w_kernel(const float* __restrict__ w, const float* __restrict__ b00){
    __shared__ float s_q[CIN];
    __shared__ float s_sc[CIN];
    __shared__ float s_m0[8];
    int t = threadIdx.x;
    const float inv = 1.f / (float)NTOT;
    if (t < CIN){
        float s = 0.f, q = 0.f;
        for (int b = 0; b < NB; b++){ s += g_psum[b][t]; q += g_psq[b][t]; }
        s_q[t] = q;
        if (t < 8){ s_m0[t] = s * inv; }
    }
    __syncthreads();
    if (t < CIN){
        float norm;
        if (t < 8){
            norm = s_q[t] * inv - s_m0[t]*s_m0[t];
        } else if (t < 32){
            int c0 = 8 + ((t-8)/3)*3;
            norm = (s_q[c0] + s_q[c0+1] + s_q[c0+2]) * inv;
        } else {
            int c0 = 32 + ((t-32)/5)*5;
            norm = (s_q[c0] + s_q[c0+1] + s_q[c0+2] + s_q[c0+3] + s_q[c0+4]) * inv;
        }
        float sc = 1.f / sqrtf(norm + 1e-5f);
        s_sc[t] = sc; g_sc[t] = sc;
    }
    __syncthreads();
    if (t < COUT){
        if (t >= 8){ g_bias[t] = 0.f; }
        else {
            float id0 = 0.f, id1 = 0.f;
            for (int tap = 0; tap < 27; tap++){ id0 += b00[tap]; id1 += b00[27 + tap]; }
            float bia = 0.f;
            for (int v = 0; v < 8; v++){
                const float* wp = w + (t*8 + v)*2;
                bia -= (wp[0]*id0 + wp[1]*id1) * s_sc[v] * s_m0[v];
            }
            g_bias[t] = bia;
        }
    }
    __syncthreads();
    for (int k = t; k < 1152; k += blockDim.x){
        int u = k & 7;
        int b2 = (k >> 3) & 1;
        int g = (k >> 4) % 24;
        int i = k / 384;
        int j = g >> 3, v = g & 7;
        int dj = (j == 0) ? 1 : (j == 1 ? 3 : 5);
        int fo = (j == 0) ? 0 : (j == 1 ? 8 : 32);
        int sel = i*3 + j;
        float val = w[sel*128 + (u*8 + v)*2 + b2] * s_sc[fo + v*dj];
        u64 dup; asm("mov.b64 %0, {%1, %1};" : "=l"(dup) : "f"(val));
        g_w2d[k] = dup;
    }
}

// -------- 4) B: pointwise mix, one s-slice per block, 8 voxels/thread --------
#define NV8 (OSPAT/8)    // 3375

__global__ __launch_bounds__(128) void mix_kernel(float* __restrict__ out){
    __shared__ u64 sw[384];      // this i-slice's duplicated weights [gb][u]
    __shared__ float sb[8];
    const int tid = threadIdx.x;
    const int b   = blockIdx.y;
    const int s   = blockIdx.z;  // 0..8
    int i, d; s_to_id(s, i, d);
    const int di = (i == 0) ? 1 : (i == 1 ? 3 : 5);
    const int fo = (i == 0) ? 0 : (i == 1 ? 8 : 32);

    for (int k = tid; k < 384; k += 128) sw[k] = g_w2d[i*384 + k];
    if (tid < 8) sb[tid] = g_bias[tid];
    __syncthreads();

    const int v8 = blockIdx.x * 128 + tid;
    if (v8 >= NV8) return;
    const int vox = v8 * 8;

    // s-major z: 48 contiguous channel rows starting at s*48
    const float* zs = g_z + ((size_t)b*432u + (size_t)s*48u)*OSPAT + vox;
    float* ob = out + (size_t)b*COUT*OSPAT + vox;

    u64 acc[8][4];
    #pragma unroll
    for (int u = 0; u < 8; u++){
        u64 ini = (i == 0) ? pack2(sb[u]) : 0ULL;
        acc[u][0] = ini; acc[u][1] = ini; acc[u][2] = ini; acc[u][3] = ini;
    }
    #pragma unroll 4
    for (int gb = 0; gb < 48; gb++){
        const float* zp = zs + (size_t)gb*OSPAT;
        ulonglong2 za = *reinterpret_cast<const ulonglong2*>(zp);
        ulonglong2 zc = *reinterpret_cast<const ulonglong2*>(zp + 4);
        const u64* wrow = sw + gb*8;
        #pragma unroll
        for (int u = 0; u < 8; u++){
            u64 wv = wrow[u];
            fma2(acc[u][0], za.x, wv);
            fma2(acc[u][1], za.y, wv);
            fma2(acc[u][2], zc.x, wv);
            fma2(acc[u][3], zc.y, wv);
        }
    }
    #pragma unroll
    for (int u = 0; u < 8; u++){
        float4 r0, r1;
        unpack2(acc[u][0], r0.x, r0.y);
        unpack2(acc[u][1], r0.z, r0.w);
        unpack2(acc[u][2], r1.x, r1.y);
        unpack2(acc[u][3], r1.z, r1.w);
        float* op = ob + (size_t)(fo + u*di + d)*OSPAT;
        *reinterpret_cast<float4*>(op)     = r0;
        *reinterpret_cast<float4*>(op + 4) = r1;
    }
}

// -------- launch --------
extern "C" void kernel_launch(void* const* d_in, const int* in_sizes, int n_in,
                              void* d_out, int out_size){
    const float* x = (const float*)d_in[0];
    const float* w = (const float*)d_in[1];
    const float* B[9];
    for (int k = 0; k < 9; k++) B[k] = (const float*)d_in[2 + k];

    init_kernel<<<6, 1024>>>(B[0], B[1], B[2], B[3], B[4], B[5], B[6], B[7], B[8]);
    basis_conv<<<dim3(2, 30, 192), 128>>>(x);
    prep_w_kernel<<<1, 128>>>(w, B[0]);
    mix_kernel<<<dim3((NV8 + 127)/128, NB, 9), 128>>>((float*)d_out);  // 4th launch -> profiled
}

// round 17
// speedup vs baseline: 1.1262x; 1.1262x over previous
#include <cuda_runtime.h>
#include <cstdint>

#define CIN 72
#define COUT 72
#define NSPAT 32768          // 32*32*32
#define NB 8
#define NTOT (NB*NSPAT)
#define OD 30
#define OSPAT (OD*OD*OD)     // 27000

typedef unsigned long long u64;
typedef unsigned int u32;

// -------- device scratch (no allocations allowed) --------
__device__ float g_psum[NB][CIN];
__device__ float g_psq[NB][CIN];
__device__ float g_sc[CIN];
__device__ float g_mean0[8];
__device__ float g_bias[COUT];
__device__ float g_C[4374];            // basis coeffs per j: [(e*27+tap)*18 + (b2*9+s)]
__device__ u64   g_w2d[3*24*2*8];      // duplicated {w,w}: [i][(g*2+b2)*8+u]
__device__ __align__(16) float g_z[(size_t)NB*432u*27000u];   // intermediate (373 MB)

// -------- packed f32x2 helpers --------
__device__ __forceinline__ u64 pack2(float a){
    u64 r; asm("mov.b64 %0, {%1, %1};" : "=l"(r) : "f"(a)); return r;
}
__device__ __forceinline__ void fma2(u64& d, u64 a, u64 b){
    asm("fma.rn.f32x2 %0, %1, %2, %0;" : "+l"(d) : "l"(a), "l"(b));
}
__device__ __forceinline__ void unpack2(u64 v, float& lo, float& hi){
    asm("mov.b64 {%0, %1}, %2;" : "=f"(lo), "=f"(hi) : "l"(v));
}
__device__ __forceinline__ u32 smem_u32(const void* p){
    u32 a; asm("{ .reg .u64 t; cvta.to.shared.u64 t, %1; cvt.u32.u64 %0, t; }" : "=r"(a) : "l"(p));
    return a;
}
__device__ __forceinline__ void cp16(u32 dst, const void* src){
    asm volatile("cp.async.ca.shared.global [%0], [%1], 16;" :: "r"(dst), "l"(src));
}
__device__ __forceinline__ void cp_commit(){ asm volatile("cp.async.commit_group;" ::: "memory"); }
__device__ __forceinline__ void cp_wait_all(){ asm volatile("cp.async.wait_group 0;" ::: "memory"); }

__device__ __forceinline__ void s_to_id(int s, int& i, int& d){
    if (s == 0){ i = 0; d = 0; }
    else if (s < 4){ i = 1; d = s - 1; }
    else { i = 2; d = s - 4; }
}

// -------- 1) per-(batch,channel) sum / sumsq --------
__global__ void stats_kernel(const float* __restrict__ x){
    int c = blockIdx.x, b = blockIdx.y;
    float s = 0.f, q = 0.f;
    const float4* p = reinterpret_cast<const float4*>(x + ((size_t)b*CIN + c)*NSPAT);
    for (int i = threadIdx.x; i < NSPAT/4; i += blockDim.x){
        float4 v = p[i];
        s += v.x + v.y + v.z + v.w;
        q += v.x*v.x + v.y*v.y + v.z*v.z + v.w*v.w;
    }
    __shared__ float ss[256];
    __shared__ float sq[256];
    int t = threadIdx.x;
    ss[t] = s; sq[t] = q;
    __syncthreads();
    for (int ofs = 128; ofs > 0; ofs >>= 1){
        if (t < ofs){ ss[t] += ss[t+ofs]; sq[t] += sq[t+ofs]; }
        __syncthreads();
    }
    if (t == 0){ g_psum[b][c] = ss[0]; g_psq[b][c] = sq[0]; }
}

// -------- 2) merged prep (scales/means/bias) + build (C table + dup weights) --------
__global__ void prep_build_kernel(const float* __restrict__ w,
    const float* b00, const float* b01, const float* b02,
    const float* b10, const float* b11, const float* b12,
    const float* b20, const float* b21, const float* b22){
    __shared__ float s_q[CIN];
    __shared__ float s_sc[CIN];
    __shared__ float s_m0[8];
    int t = threadIdx.x;
    const float inv = 1.f / (float)NTOT;
    if (t < CIN){
        float s = 0.f, q = 0.f;
        for (int b = 0; b < NB; b++){ s += g_psum[b][t]; q += g_psq[b][t]; }
        s_q[t] = q;
        if (t < 8){ float m = s * inv; s_m0[t] = m; g_mean0[t] = m; }
    }
    __syncthreads();
    if (t < CIN){
        float norm;
        if (t < 8){
            norm = s_q[t] * inv - s_m0[t]*s_m0[t];
        } else if (t < 32){
            int c0 = 8 + ((t-8)/3)*3;
            norm = (s_q[c0] + s_q[c0+1] + s_q[c0+2]) * inv;
        } else {
            int c0 = 32 + ((t-32)/5)*5;
            norm = (s_q[c0] + s_q[c0+1] + s_q[c0+2] + s_q[c0+3] + s_q[c0+4]) * inv;
        }
        float sc = 1.f / sqrtf(norm + 1e-5f);
        s_sc[t] = sc; g_sc[t] = sc;
    }
    __syncthreads();
    if (t < COUT){
        if (t >= 8){ g_bias[t] = 0.f; }
        else {
            float id0 = 0.f, id1 = 0.f;
            for (int tap = 0; tap < 27; tap++){ id0 += b00[tap]; id1 += b00[27 + tap]; }
            float bia = 0.f;
            for (int v = 0; v < 8; v++){
                const float* wp = w + (t*8 + v)*2;
                bia -= (wp[0]*id0 + wp[1]*id1) * s_sc[v] * s_m0[v];
            }
            g_bias[t] = bia;
        }
    }
    // build phase
    for (int idx = t; idx < 4374 + 1152; idx += blockDim.x){
        if (idx < 4374){
            int j, off;
            if (idx < 486){ j = 0; off = 0; }
            else if (idx < 1944){ j = 1; off = 486; }
            else { j = 2; off = 1944; }
            int rem = idx - off;
            int tt  = rem % 18;
            int et  = rem / 18;
            int tap = et % 27;
            int e   = et / 27;
            int b2  = tt / 9, s = tt % 9;
            int i, d; s_to_id(s, i, d);
            int di = (i == 0) ? 1 : (i == 1 ? 3 : 5);
            int dj = (j == 0) ? 1 : (j == 1 ? 3 : 5);
            const float* bas;
            int sel = i*3 + j;
            switch (sel){
                case 0: bas = b00; break; case 1: bas = b01; break; case 2: bas = b02; break;
                case 3: bas = b10; break; case 4: bas = b11; break; case 5: bas = b12; break;
                case 6: bas = b20; break; case 7: bas = b21; break; default: bas = b22; break;
            }
            g_C[idx] = bas[((b2*di + d)*dj + e)*27 + tap];
        } else {
            int k = idx - 4374;
            int u = k & 7;
            int b2 = (k >> 3) & 1;
            int g = (k >> 4) % 24;
            int i = k / 384;
            int j = g >> 3, v = g & 7;
            int dj = (j == 0) ? 1 : (j == 1 ? 3 : 5);
            int fo = (j == 0) ? 0 : (j == 1 ? 8 : 32);
            int sel = i*3 + j;
            float val = w[sel*128 + (u*8 + v)*2 + b2] * s_sc[fo + v*dj];
            u64 dup; asm("mov.b64 %0, {%1, %1};" : "=l"(dup) : "f"(val));
            g_w2d[k] = dup;
        }
    }
}

// -------- 3) A: basis conv, ALL batches in one launch; dj-interleaved schedule --------
__global__ __launch_bounds__(128) void basis_conv(const float* __restrict__ x){
    __shared__ __align__(16) float sC[2430];
    __shared__ __align__(16) float sX[9720];          // [e][z3][y18][36]

    const int tid = threadIdx.x;
    const int xg  = tid & 7;
    const int yr  = tid >> 3;            // 0..15
    const int x0  = xg << 2;
    const int yt  = blockIdx.x;          // 0..1
    const int oz  = blockIdx.y;          // 0..29
    const int zi  = blockIdx.z;          // 0..191
    const int b   = zi / 24;
    const int gi  = zi % 24;
    const int g   = (gi % 3) * 8 + (gi / 3);   // interleave dj = 1,3,5,...
    const int y0  = yt * 16;

    const int j  = g >> 3, v = g & 7;
    const int dj = (j == 0) ? 1 : (j == 1 ? 3 : 5);
    const int fo = (j == 0) ? 0 : (j == 1 ? 8 : 32);
    const int coff = (j == 0) ? 0 : (j == 1 ? 486 : 1944);

    const float* xc = x + ((size_t)b*CIN + fo + v*dj)*NSPAT;

    const int csz = dj * 486;
    for (int k = tid; k < csz; k += 128) sC[k] = g_C[coff + k];

    const u32 sxa = smem_u32(sX);
    const int nrows = dj * 54;
    for (int r8 = tid; r8 < nrows*8; r8 += 128){
        int r = r8 >> 3, seg = r8 & 7;
        int e = r / 54, rem = r % 54, zz = rem / 18, yy = rem % 18;
        int ys = y0 + yy; if (ys > 31) ys = 31;
        cp16(sxa + (u32)(r*36 + seg*4)*4, xc + (size_t)e*NSPAT + (oz+zz)*1024 + ys*32 + seg*4);
    }
    for (int k = tid; k < nrows*4; k += 128){
        int r = k >> 2, c = 32 + (k & 3);
        sX[r*36 + c] = 0.f;
    }
    cp_commit(); cp_wait_all();
    __syncthreads();

    u64 acc[9][4];
    #pragma unroll
    for (int tp = 0; tp < 9; tp++)
        #pragma unroll
        for (int vx = 0; vx < 4; vx++) acc[tp][vx] = 0ULL;

    for (int e = 0; e < dj; e++){
        #pragma unroll
        for (int kz = 0; kz < 3; kz++){
            #pragma unroll
            for (int ky = 0; ky < 3; ky++){
                const float* row = &sX[(((e*3 + kz)*18) + yr + ky)*36 + x0];
                float4 f4 = *reinterpret_cast<const float4*>(row);
                float2 f2 = *reinterpret_cast<const float2*>(row + 4);
                u64 X[6];
                X[0] = pack2(f4.x); X[1] = pack2(f4.y); X[2] = pack2(f4.z);
                X[3] = pack2(f4.w); X[4] = pack2(f2.x); X[5] = pack2(f2.y);
                const int tapb = kz*9 + ky*3;
                #pragma unroll
                for (int kx = 0; kx < 3; kx++){
                    const float* cb = &sC[(e*27 + tapb + kx)*18];
                    #pragma unroll
                    for (int tp = 0; tp < 9; tp++){
                        u64 c2 = *reinterpret_cast<const u64*>(cb + 2*tp);
                        fma2(acc[tp][0], c2, X[kx]);
                        fma2(acc[tp][1], c2, X[kx+1]);
                        fma2(acc[tp][2], c2, X[kx+2]);
                        fma2(acc[tp][3], c2, X[kx+3]);
                    }
                }
            }
        }
    }

    const int oy = y0 + yr;
    if (oy < OD){
        const size_t vbase = (size_t)(oz*OD + oy)*OD;
        float* zb = g_z + (size_t)b*432u*OSPAT;
        #pragma unroll
        for (int tp = 0; tp < 9; tp++){
            float* zlo = zb + (size_t)(g*18 + 2*tp) * OSPAT + vbase;
            float* zhi = zlo + OSPAT;
            #pragma unroll
            for (int vx = 0; vx < 4; vx++){
                int ox = x0 + vx;
                float lo, hi; unpack2(acc[tp][vx], lo, hi);
                if (ox < OD){ zlo[ox] = lo; zhi[ox] = hi; }
            }
        }
    }
}

// -------- 4) B: pointwise mix, one s-slice per block, 2 voxels/thread --------
#define NV2 (OSPAT/2)    // 13500

__global__ __launch_bounds__(128) void mix_kernel(float* __restrict__ out){
    __shared__ u64 sw[384];      // this i-slice's duplicated weights [gb][u]
    __shared__ float sb[8];
    const int tid = threadIdx.x;
    const int b   = blockIdx.y;
    const int s   = blockIdx.z;  // 0..8
    int i, d; s_to_id(s, i, d);
    const int di = (i == 0) ? 1 : (i == 1 ? 3 : 5);
    const int fo = (i == 0) ? 0 : (i == 1 ? 8 : 32);

    for (int k = tid; k < 384; k += 128) sw[k] = g_w2d[i*384 + k];
    if (tid < 8) sb[tid] = g_bias[tid];
    __syncthreads();

    const int v2 = blockIdx.x * 128 + tid;
    if (v2 >= NV2) return;
    const int vox = v2 * 2;

    const float* zb = g_z + (size_t)b*432u*OSPAT + vox;
    float* ob = out + (size_t)b*COUT*OSPAT + vox;

    u64 acc[8];
    #pragma unroll
    for (int u = 0; u < 8; u++)
        acc[u] = (i == 0) ? pack2(sb[u]) : 0ULL;

    #pragma unroll 8
    for (int gb = 0; gb < 48; gb++){
        const int gg = gb >> 1, be = gb & 1;
        const int ch = gg*18 + be*9 + s;
        u64 zz = *reinterpret_cast<const u64*>(zb + (size_t)ch*OSPAT);
        const u64* wrow = sw + gb*8;
        #pragma unroll
        for (int u = 0; u < 8; u++)
            fma2(acc[u], zz, wrow[u]);
    }
    #pragma unroll
    for (int u = 0; u < 8; u++){
        float2 r;
        unpack2(acc[u], r.x, r.y);
        *reinterpret_cast<float2*>(ob + (size_t)(fo + u*di + d)*OSPAT) = r;
    }
}

// -------- launch --------
extern "C" void kernel_launch(void* const* d_in, const int* in_sizes, int n_in,
                              void* d_out, int out_size){
    const float* x = (const float*)d_in[0];
    const float* w = (const float*)d_in[1];
    const float* B[9];
    for (int k = 0; k < 9; k++) B[k] = (const float*)d_in[2 + k];

    stats_kernel<<<dim3(CIN, NB), 256>>>(x);
    prep_build_kernel<<<1, 1024>>>(w, B[0], B[1], B[2], B[3], B[4], B[5], B[6], B[7], B[8]);
    basis_conv<<<dim3(2, 30, 192), 128>>>(x);
    mix_kernel<<<dim3((NV2 + 127)/128, NB, 9), 128>>>((float*)d_out);  // 4th launch -> profiled
}